// round 12
// baseline (speedup 1.0000x reference)
#include <cuda_runtime.h>
#include <cuda_fp16.h>
#include <cstdint>

#define B   2
#define S   2048
#define H   16
#define HD  64
#define DIM 1024
#define EPS 1e-5f
#define QSTR 72         // half smem row stride (conflict-free for ldmatrix + mma frags)
#define QSCALE 0.180336879f   // log2(e)/8 folded into q1/q2 at projection time

// ---------------- scratch (device globals; allocation-free rule) -------------
__device__ __align__(16) __half g_q1h[(size_t)B*H*S*HD];
__device__ __align__(16) __half g_k1h[(size_t)B*H*S*HD];
__device__ __align__(16) __half g_q2h[(size_t)B*H*S*HD];
__device__ __align__(16) __half g_k2h[(size_t)B*H*S*HD];
__device__ __align__(16) __half g_vph[(size_t)B*H*S*HD];
__device__ __align__(16) __half g_aoh[(size_t)B*S*DIM];
__device__ __align__(16) __half g_woh[(size_t)DIM*DIM];

// ---------------- asm helpers -------------------------------------------------
__device__ __forceinline__ void mma16816(float* d, uint32_t a0, uint32_t a1,
                                         uint32_t a2, uint32_t a3,
                                         uint32_t b0, uint32_t b1) {
    asm volatile(
        "mma.sync.aligned.m16n8k16.row.col.f32.f16.f16.f32 "
        "{%0,%1,%2,%3}, {%4,%5,%6,%7}, {%8,%9}, {%0,%1,%2,%3};\n"
        : "+f"(d[0]), "+f"(d[1]), "+f"(d[2]), "+f"(d[3])
        : "r"(a0), "r"(a1), "r"(a2), "r"(a3), "r"(b0), "r"(b1));
}

__device__ __forceinline__ uint4 ldsm_x4(uint32_t addr) {
    uint4 r;
    asm volatile("ldmatrix.sync.aligned.m8n8.x4.shared.b16 {%0,%1,%2,%3}, [%4];"
                 : "=r"(r.x), "=r"(r.y), "=r"(r.z), "=r"(r.w) : "r"(addr));
    return r;
}
__device__ __forceinline__ uint4 ldsm_x4_trans(uint32_t addr) {
    uint4 r;
    asm volatile("ldmatrix.sync.aligned.m8n8.x4.trans.shared.b16 {%0,%1,%2,%3}, [%4];"
                 : "=r"(r.x), "=r"(r.y), "=r"(r.z), "=r"(r.w) : "r"(addr));
    return r;
}

__device__ __forceinline__ void cp_async16(uint32_t saddr, const void* gptr) {
    asm volatile("cp.async.cg.shared.global [%0], [%1], 16;\n"
                 :: "r"(saddr), "l"(gptr));
}
__device__ __forceinline__ void cp_commit() {
    asm volatile("cp.async.commit_group;\n");
}
template <int N> __device__ __forceinline__ void cp_wait() {
    asm volatile("cp.async.wait_group %0;\n" :: "n"(N));
}

// A-fragment (16x16 tile at row0, k-chunk kc) via ldmatrix.x4
__device__ __forceinline__ uint4 lda_frag(uint32_t base, int row0, int kc, int lane) {
    uint32_t addr = base + 2u * ((uint32_t)(row0 + (lane & 7) + ((lane >> 3) & 1) * 8) * QSTR
                                 + kc * 16 + ((lane >> 4) & 1) * 8);
    return ldsm_x4(addr);
}
// B-fragment pair (two 8-wide n-tiles at ntp*16, k-chunk kc) via ldmatrix.x4
__device__ __forceinline__ uint4 ldb_frag(uint32_t base, int ntp, int kc, int lane) {
    uint32_t addr = base + 2u * ((uint32_t)(ntp * 16 + ((lane >> 4) & 1) * 8 + (lane & 7)) * QSTR
                                 + kc * 16 + ((lane >> 3) & 1) * 8);
    return ldsm_x4(addr);
}

// exp2 one nt-group of scores -> packed fp16 P, accumulate row sums
__device__ __forceinline__ void exp_group(const float* s, int nt, uint32_t* P,
                                          float& la, float& lb) {
    float e0 = exp2f(s[4*nt  ]);
    float e1 = exp2f(s[4*nt+1]);
    float e2 = exp2f(s[4*nt+2]);
    float e3 = exp2f(s[4*nt+3]);
    la += e0 + e1;
    lb += e2 + e3;
    __half2 h01 = __floats2half2_rn(e0, e1);
    __half2 h23 = __floats2half2_rn(e2, e3);
    P[2*nt]   = *(uint32_t*)&h01;
    P[2*nt+1] = *(uint32_t*)&h23;
}

// ---------------- kernel 0: wo fp32 -> fp16 -----------------------------------
__global__ void convert_wo_kernel(const float* __restrict__ wo) {
    int i = (blockIdx.x * 256 + threadIdx.x) * 2;
    float2 f = *(const float2*)&wo[i];
    *(__half2*)&g_woh[i] = __floats2half2_rn(f.x, f.y);
}

// ---------------- kernel 1: per-head projections (HMMA) -----------------------
__device__ __forceinline__ void hmma_16x64_scalar(const __half* __restrict__ sA,
                                                  const __half* __restrict__ sB,
                                                  int warp, int g, int l, float* acc) {
    #pragma unroll
    for (int kc = 0; kc < 4; kc++) {
        uint32_t a0 = *(const uint32_t*)&sA[(warp*16+g  )*QSTR + kc*16 + 2*l    ];
        uint32_t a1 = *(const uint32_t*)&sA[(warp*16+g+8)*QSTR + kc*16 + 2*l    ];
        uint32_t a2 = *(const uint32_t*)&sA[(warp*16+g  )*QSTR + kc*16 + 2*l + 8];
        uint32_t a3 = *(const uint32_t*)&sA[(warp*16+g+8)*QSTR + kc*16 + 2*l + 8];
        #pragma unroll
        for (int nt = 0; nt < 8; nt++) {
            uint32_t b0 = *(const uint32_t*)&sB[(nt*8+g)*QSTR + kc*16 + 2*l    ];
            uint32_t b1 = *(const uint32_t*)&sB[(nt*8+g)*QSTR + kc*16 + 2*l + 8];
            mma16816(&acc[nt*4], a0, a1, a2, a3, b0, b1);
        }
    }
}

__global__ __launch_bounds__(256, 1) void proj_kernel(
        const float* __restrict__ q, const float* __restrict__ k,
        const float* __restrict__ v,
        const float* __restrict__ wq1, const float* __restrict__ wk1,
        const float* __restrict__ wq2, const float* __restrict__ wk2,
        const float* __restrict__ wv) {
    extern __shared__ __half smp[];
    __half* sX = smp;               // 3 x [128][QSTR]
    __half* sW = smp + 3*128*QSTR;  // 5 x [64][QSTR]

    const int bh = blockIdx.x, b = bh / H, h = bh % H;
    const int s0 = blockIdx.y * 128;
    const int tid = threadIdx.x;
    const int warp = tid >> 5, lane = tid & 31;
    const int g = lane >> 2, l = lane & 3;

    const float* xsrc[3] = {q, k, v};
    #pragma unroll
    for (int w = 0; w < 3; w++) {
        for (int i = tid; i < 128*32; i += 256) {
            int r = i >> 5, c = (i & 31) * 2;
            float2 f = *(const float2*)&xsrc[w][((size_t)(b*S + s0 + r))*DIM + h*HD + c];
            *(__half2*)&sX[w*128*QSTR + r*QSTR + c] = __floats2half2_rn(f.x, f.y);
        }
    }
    const float* wsrc[5] = {wq1, wk1, wq2, wk2, wv};
    #pragma unroll
    for (int w = 0; w < 5; w++) {
        const float* src = wsrc[w] + (size_t)h*HD*HD;
        for (int i = tid; i < 64*32; i += 256) {
            int r = i >> 5, c = (i & 31) * 2;
            float2 f = *(const float2*)&src[r*64 + c];
            *(__half2*)&sW[w*64*QSTR + r*QSTR + c] = __floats2half2_rn(f.x, f.y);
        }
    }
    __syncthreads();

    __half* dsts[5] = {g_q1h, g_k1h, g_q2h, g_k2h, g_vph};
    const int xsel[5] = {0, 1, 0, 1, 2};
    #pragma unroll
    for (int w = 0; w < 5; w++) {
        float acc[32];
        #pragma unroll
        for (int i = 0; i < 32; i++) acc[i] = 0.f;
        hmma_16x64_scalar(sX + xsel[w]*128*QSTR, sW + w*64*QSTR, warp, g, l, acc);
        // fold softmax scale (log2e/8) into q1 (w==0) and q2 (w==2)
        const float sc = (w == 0 || w == 2) ? QSCALE : 1.f;
        __half* dst = dsts[w] + ((size_t)bh*S + s0)*HD;
        #pragma unroll
        for (int nt = 0; nt < 8; nt++) {
            int col = nt*8 + 2*l;
            *(__half2*)&dst[(warp*16+g  )*HD + col] =
                __floats2half2_rn(acc[4*nt  ]*sc, acc[4*nt+1]*sc);
            *(__half2*)&dst[(warp*16+g+8)*HD + col] =
                __floats2half2_rn(acc[4*nt+2]*sc, acc[4*nt+3]*sc);
        }
    }
}

// ---------------- kernel 2: dual attention, software-pipelined stages ---------
// Per tile: QK1 -> [QK2 || exp1] -> [PV1 || exp2] -> PV2. Each MUFU burst is
// interleaved kc-chunk-wise with an independent tensor phase; peak regs stay
// at the proven no-spill level (never both P arrays + o live at once).
#define KV_TILE_H (64*QSTR)   // halves per K/V stage array
#define ATHR 128              // attention CTA threads
#define AQ   64               // attention q-rows per CTA

__global__ __launch_bounds__(ATHR, 3) void attn_kernel(const float* __restrict__ gain_p) {
    extern __shared__ __half smh[];
    __half* sQ1 = smh;                  // [AQ][QSTR]
    __half* sQ2 = sQ1 + AQ*QSTR;
    __half* sKV = sQ2 + AQ*QSTR;        // 2 stages x {K1,K2,V} x [64][QSTR]

    const int bh = blockIdx.x;
    const int s0 = blockIdx.y * AQ;
    const int tid = threadIdx.x;
    const int warp = tid >> 5, lane = tid & 31;
    const int g = lane >> 2, l = lane & 3;
    const size_t base = (size_t)bh * S * HD;

    for (int i = tid; i < AQ*32; i += ATHR) {
        int r = i >> 5, c = (i & 31) * 2;
        size_t gi = base + (size_t)(s0 + r)*HD + c;
        *(__half2*)&sQ1[r*QSTR+c] = *(const __half2*)&g_q1h[gi];
        *(__half2*)&sQ2[r*QSTR+c] = *(const __half2*)&g_q2h[gi];
    }

    const uint32_t skv_u = (uint32_t)__cvta_generic_to_shared(sKV);
    const uint32_t q1u = (uint32_t)__cvta_generic_to_shared(sQ1);
    const uint32_t q2u = (uint32_t)__cvta_generic_to_shared(sQ2);
    const __half* gsrc[3] = {g_k1h, g_k2h, g_vph};

    auto issue_tile = [&](int kt, int st) {
        #pragma unroll
        for (int a = 0; a < 3; a++) {
            #pragma unroll
            for (int t = 0; t < 4; t++) {
                int chunk = tid + t*ATHR;       // 512 chunks of 16B per array
                int r = chunk >> 3, c8 = (chunk & 7) * 8;
                uint32_t sa = skv_u + (uint32_t)((st*3 + a)*KV_TILE_H + r*QSTR + c8) * 2;
                cp_async16(sa, gsrc[a] + base + (size_t)(kt*64 + r)*HD + c8);
            }
        }
        cp_commit();
    };

    float o1[32], o2[32];
    #pragma unroll
    for (int i = 0; i < 32; i++) { o1[i] = 0.f; o2[i] = 0.f; }
    float l1a = 0.f, l1b = 0.f, l2a = 0.f, l2b = 0.f;

    const int KT = S/64;
    issue_tile(0, 0);
    for (int kt = 0; kt < KT; kt++) {
        const int cur = kt & 1;
        cp_wait<0>();          // tile kt arrived
        __syncthreads();       // all warps done reading stage cur^1 AND see tile kt
        if (kt + 1 < KT) issue_tile(kt+1, cur ^ 1);
        const uint32_t sk1u = skv_u + (uint32_t)((cur*3    )*KV_TILE_H)*2;
        const uint32_t sk2u = skv_u + (uint32_t)((cur*3 + 1)*KV_TILE_H)*2;
        const uint32_t svu  = skv_u + (uint32_t)((cur*3 + 2)*KV_TILE_H)*2;

        // ---- stage A: QK1 -> s1 -------------------------------------------
        float s1[32];
        #pragma unroll
        for (int i = 0; i < 32; i++) s1[i] = 0.f;
        #pragma unroll
        for (int kc = 0; kc < 4; kc++) {
            uint4 af = lda_frag(q1u, warp*16, kc, lane);
            #pragma unroll
            for (int ntp = 0; ntp < 4; ntp++) {
                uint4 bf = ldb_frag(sk1u, ntp, kc, lane);
                mma16816(&s1[(2*ntp  )*4], af.x, af.y, af.z, af.w, bf.x, bf.y);
                mma16816(&s1[(2*ntp+1)*4], af.x, af.y, af.z, af.w, bf.z, bf.w);
            }
        }
        // ---- stage B: QK2 (tensor) interleaved with exp1 (MUFU) -----------
        float s2[32];
        #pragma unroll
        for (int i = 0; i < 32; i++) s2[i] = 0.f;
        uint32_t P1[16];
        #pragma unroll
        for (int kc = 0; kc < 4; kc++) {
            uint4 af = lda_frag(q2u, warp*16, kc, lane);
            #pragma unroll
            for (int ntp = 0; ntp < 4; ntp++) {
                uint4 bf = ldb_frag(sk2u, ntp, kc, lane);
                mma16816(&s2[(2*ntp  )*4], af.x, af.y, af.z, af.w, bf.x, bf.y);
                mma16816(&s2[(2*ntp+1)*4], af.x, af.y, af.z, af.w, bf.z, bf.w);
            }
            exp_group(s1, 2*kc,   P1, l1a, l1b);
            exp_group(s1, 2*kc+1, P1, l1a, l1b);
        }
        // ---- stage C: PV1 (tensor) interleaved with exp2 (MUFU) -----------
        uint32_t P2[16];
        #pragma unroll
        for (int kc = 0; kc < 4; kc++) {
            uint32_t a0 = P1[4*kc], a1 = P1[4*kc+1], a2 = P1[4*kc+2], a3 = P1[4*kc+3];
            #pragma unroll
            for (int ntp = 0; ntp < 4; ntp++) {
                uint32_t addr = svu + 2u * ((uint32_t)(kc*16 + (lane & 15)) * QSTR
                                            + ntp*16 + ((lane >> 4) & 1) * 8);
                uint4 bf = ldsm_x4_trans(addr);
                mma16816(&o1[(2*ntp  )*4], a0, a1, a2, a3, bf.x, bf.y);
                mma16816(&o1[(2*ntp+1)*4], a0, a1, a2, a3, bf.z, bf.w);
            }
            exp_group(s2, 2*kc,   P2, l2a, l2b);
            exp_group(s2, 2*kc+1, P2, l2a, l2b);
        }
        // ---- stage D: PV2 -------------------------------------------------
        #pragma unroll
        for (int kc = 0; kc < 4; kc++) {
            uint32_t a0 = P2[4*kc], a1 = P2[4*kc+1], a2 = P2[4*kc+2], a3 = P2[4*kc+3];
            #pragma unroll
            for (int ntp = 0; ntp < 4; ntp++) {
                uint32_t addr = svu + 2u * ((uint32_t)(kc*16 + (lane & 15)) * QSTR
                                            + ntp*16 + ((lane >> 4) & 1) * 8);
                uint4 bf = ldsm_x4_trans(addr);
                mma16816(&o2[(2*ntp  )*4], a0, a1, a2, a3, bf.x, bf.y);
                mma16816(&o2[(2*ntp+1)*4], a0, a1, a2, a3, bf.z, bf.w);
            }
        }
    }

    l1a += __shfl_xor_sync(0xffffffffu, l1a, 1); l1a += __shfl_xor_sync(0xffffffffu, l1a, 2);
    l1b += __shfl_xor_sync(0xffffffffu, l1b, 1); l1b += __shfl_xor_sync(0xffffffffu, l1b, 2);
    l2a += __shfl_xor_sync(0xffffffffu, l2a, 1); l2a += __shfl_xor_sync(0xffffffffu, l2a, 2);
    l2b += __shfl_xor_sync(0xffffffffu, l2b, 1); l2b += __shfl_xor_sync(0xffffffffu, l2b, 2);

    const float gain = *gain_p;
    const float i1a = 1.f/l1a, i1b = 1.f/l1b, i2a = 1.f/l2a, i2b = 1.f/l2b;

    float va[16], vb[16];
    #pragma unroll
    for (int nt = 0; nt < 8; nt++) {
        va[2*nt]   = o1[4*nt  ]*i1a - gain*o2[4*nt  ]*i2a;
        va[2*nt+1] = o1[4*nt+1]*i1a - gain*o2[4*nt+1]*i2a;
        vb[2*nt]   = o1[4*nt+2]*i1b - gain*o2[4*nt+2]*i2b;
        vb[2*nt+1] = o1[4*nt+3]*i1b - gain*o2[4*nt+3]*i2b;
    }
    float sa = 0.f, sb = 0.f;
    #pragma unroll
    for (int i = 0; i < 16; i++) { sa += va[i]; sb += vb[i]; }
    sa += __shfl_xor_sync(0xffffffffu, sa, 1); sa += __shfl_xor_sync(0xffffffffu, sa, 2);
    sb += __shfl_xor_sync(0xffffffffu, sb, 1); sb += __shfl_xor_sync(0xffffffffu, sb, 2);
    const float ma = sa * (1.f/64.f), mb = sb * (1.f/64.f);
    float qa = 0.f, qb = 0.f;
    #pragma unroll
    for (int i = 0; i < 16; i++) {
        float da = va[i] - ma; qa += da*da;
        float db = vb[i] - mb; qb += db*db;
    }
    qa += __shfl_xor_sync(0xffffffffu, qa, 1); qa += __shfl_xor_sync(0xffffffffu, qa, 2);
    qb += __shfl_xor_sync(0xffffffffu, qb, 1); qb += __shfl_xor_sync(0xffffffffu, qb, 2);
    const float ra = rsqrtf(qa*(1.f/64.f) + EPS);
    const float rb = rsqrtf(qb*(1.f/64.f) + EPS);

    const int b = bh / H, h = bh % H;
    const size_t rowA = (size_t)(b*S + s0 + warp*16 + g)*DIM + h*HD;
    const size_t rowB = rowA + (size_t)8*DIM;
    #pragma unroll
    for (int nt = 0; nt < 8; nt++) {
        int col = nt*8 + 2*l;
        *(__half2*)&g_aoh[rowA + col] = __floats2half2_rn((va[2*nt]-ma)*ra, (va[2*nt+1]-ma)*ra);
        *(__half2*)&g_aoh[rowB + col] = __floats2half2_rn((vb[2*nt]-mb)*rb, (vb[2*nt+1]-mb)*rb);
    }
}

// ---------------- kernel 3: out = ao @ wo^T (HMMA, 3-stage cp.async) ----------
#define OG_STAGE_H (2*128*QSTR)  // halves per stage (A tile + W tile)
#define OG_NSTAGE 3

__global__ __launch_bounds__(256, 1) void out_gemm_kernel(float* __restrict__ out) {
    extern __shared__ __half smg[];
    const int n0 = blockIdx.x * 128;
    const int e0 = blockIdx.y * 128;
    const int tid = threadIdx.x;
    const int warp = tid >> 5, lane = tid & 31;
    const int g = lane >> 2, l = lane & 3;
    const uint32_t smg_u = (uint32_t)__cvta_generic_to_shared(smg);

    auto issue_tile = [&](int kt, int st) {
        #pragma unroll
        for (int t = 0; t < 4; t++) {            // A: 1024 chunks of 16B
            int chunk = tid + t*256;
            int r = chunk >> 3, c8 = (chunk & 7) * 8;
            uint32_t sa = smg_u + (uint32_t)(st*OG_STAGE_H + r*QSTR + c8) * 2;
            cp_async16(sa, &g_aoh[(size_t)(n0+r)*DIM + kt*64 + c8]);
        }
        #pragma unroll
        for (int t = 0; t < 4; t++) {            // W
            int chunk = tid + t*256;
            int r = chunk >> 3, c8 = (chunk & 7) * 8;
            uint32_t sa = smg_u + (uint32_t)(st*OG_STAGE_H + 128*QSTR + r*QSTR + c8) * 2;
            cp_async16(sa, &g_woh[(size_t)(e0+r)*DIM + kt*64 + c8]);
        }
        cp_commit();
    };

    float acc[64];
    #pragma unroll
    for (int i = 0; i < 64; i++) acc[i] = 0.f;

    const int KT = DIM/64;
    issue_tile(0, 0);
    issue_tile(1, 1);
    for (int kt = 0; kt < KT; kt++) {
        const int cur = kt % OG_NSTAGE;
        if (kt + 1 < KT) cp_wait<1>(); else cp_wait<0>();   // tile kt done
        __syncthreads();            // stage (kt+2)%3 last read at kt-1: free
        if (kt + 2 < KT) issue_tile(kt + 2, (kt + 2) % OG_NSTAGE);
        const uint32_t sAu = smg_u + (uint32_t)(cur*OG_STAGE_H)*2;
        const uint32_t sWu = sAu + (uint32_t)(128*QSTR)*2;
        #pragma unroll
        for (int kc = 0; kc < 4; kc++) {
            uint4 af = lda_frag(sAu, warp*16, kc, lane);
            #pragma unroll
            for (int ntp = 0; ntp < 8; ntp++) {
                uint4 bf = ldb_frag(sWu, ntp, kc, lane);
                mma16816(&acc[(2*ntp  )*4], af.x, af.y, af.z, af.w, bf.x, bf.y);
                mma16816(&acc[(2*ntp+1)*4], af.x, af.y, af.z, af.w, bf.z, bf.w);
            }
        }
        __syncthreads();            // done reading stage cur before it is refilled
    }
    #pragma unroll
    for (int nt = 0; nt < 16; nt++) {
        *(float2*)&out[(size_t)(n0+warp*16+g  )*DIM + e0 + nt*8 + 2*l] =
            make_float2(acc[4*nt], acc[4*nt+1]);
        *(float2*)&out[(size_t)(n0+warp*16+g+8)*DIM + e0 + nt*8 + 2*l] =
            make_float2(acc[4*nt+2], acc[4*nt+3]);
    }
}

// ---------------- launch ------------------------------------------------------
extern "C" void kernel_launch(void* const* d_in, const int* in_sizes, int n_in,
                              void* d_out, int out_size) {
    const float* q    = (const float*)d_in[0];
    const float* k    = (const float*)d_in[1];
    const float* v    = (const float*)d_in[2];
    const float* wq1  = (const float*)d_in[3];
    const float* wk1  = (const float*)d_in[4];
    const float* wq2  = (const float*)d_in[5];
    const float* wk2  = (const float*)d_in[6];
    const float* wv   = (const float*)d_in[7];
    const float* wo   = (const float*)d_in[8];
    const float* gain = (const float*)d_in[9];
    float* out = (float*)d_out;

    const int smem_proj = (int)((3*128 + 5*64) * QSTR * sizeof(__half));          // 101376
    const int smem_attn = (int)((2*AQ*QSTR + 6*KV_TILE_H) * sizeof(__half));      // 73728
    const int smem_gemm = (int)((OG_NSTAGE*OG_STAGE_H) * sizeof(__half));         // 110592
    static bool attr_done = false;
    if (!attr_done) {
        cudaFuncSetAttribute(proj_kernel, cudaFuncAttributeMaxDynamicSharedMemorySize, smem_proj);
        cudaFuncSetAttribute(attn_kernel, cudaFuncAttributeMaxDynamicSharedMemorySize, smem_attn);
        cudaFuncSetAttribute(out_gemm_kernel, cudaFuncAttributeMaxDynamicSharedMemorySize, smem_gemm);
        attr_done = true;
    }

    convert_wo_kernel<<<DIM*DIM/512, 256>>>(wo);

    dim3 gp(B*H, S/128);
    proj_kernel<<<gp, 256, smem_proj>>>(q, k, v, wq1, wk1, wq2, wk2, wv);

    dim3 ga(B*H, S/AQ);
    attn_kernel<<<ga, ATHR, smem_attn>>>(gain);

    dim3 gg(B*S/128, DIM/128);
    out_gemm_kernel<<<gg, 256, smem_gemm>>>(out);
}

// round 14
// speedup vs baseline: 1.1043x; 1.1043x over previous
#include <cuda_runtime.h>
#include <cuda_fp16.h>
#include <cstdint>

#define B   2
#define S   2048
#define H   16
#define HD  64
#define DIM 1024
#define EPS 1e-5f
#define QSTR 72         // half smem row stride (conflict-free for ldmatrix + mma frags)
#define QSCALE 0.180336879f   // log2(e)/8 folded into q1/q2 at projection time

// ---------------- scratch (device globals; allocation-free rule) -------------
__device__ __align__(16) __half g_q1h[(size_t)B*H*S*HD];
__device__ __align__(16) __half g_k1h[(size_t)B*H*S*HD];
__device__ __align__(16) __half g_q2h[(size_t)B*H*S*HD];
__device__ __align__(16) __half g_k2h[(size_t)B*H*S*HD];
__device__ __align__(16) __half g_vph[(size_t)B*H*S*HD];
__device__ __align__(16) __half g_aoh[(size_t)B*S*DIM];
__device__ __align__(16) __half g_woh[(size_t)DIM*DIM];

// ---------------- asm helpers -------------------------------------------------
__device__ __forceinline__ void mma16816(float* d, uint32_t a0, uint32_t a1,
                                         uint32_t a2, uint32_t a3,
                                         uint32_t b0, uint32_t b1) {
    asm volatile(
        "mma.sync.aligned.m16n8k16.row.col.f32.f16.f16.f32 "
        "{%0,%1,%2,%3}, {%4,%5,%6,%7}, {%8,%9}, {%0,%1,%2,%3};\n"
        : "+f"(d[0]), "+f"(d[1]), "+f"(d[2]), "+f"(d[3])
        : "r"(a0), "r"(a1), "r"(a2), "r"(a3), "r"(b0), "r"(b1));
}

__device__ __forceinline__ uint4 ldsm_x4(uint32_t addr) {
    uint4 r;
    asm volatile("ldmatrix.sync.aligned.m8n8.x4.shared.b16 {%0,%1,%2,%3}, [%4];"
                 : "=r"(r.x), "=r"(r.y), "=r"(r.z), "=r"(r.w) : "r"(addr));
    return r;
}
__device__ __forceinline__ uint4 ldsm_x4_trans(uint32_t addr) {
    uint4 r;
    asm volatile("ldmatrix.sync.aligned.m8n8.x4.trans.shared.b16 {%0,%1,%2,%3}, [%4];"
                 : "=r"(r.x), "=r"(r.y), "=r"(r.z), "=r"(r.w) : "r"(addr));
    return r;
}

__device__ __forceinline__ void cp_async16(uint32_t saddr, const void* gptr) {
    asm volatile("cp.async.cg.shared.global [%0], [%1], 16;\n"
                 :: "r"(saddr), "l"(gptr));
}
__device__ __forceinline__ void cp_commit() {
    asm volatile("cp.async.commit_group;\n");
}
template <int N> __device__ __forceinline__ void cp_wait() {
    asm volatile("cp.async.wait_group %0;\n" :: "n"(N));
}

// A-fragment (16x16 tile at row0, k-chunk kc) via ldmatrix.x4
__device__ __forceinline__ uint4 lda_frag(uint32_t base, int row0, int kc, int lane) {
    uint32_t addr = base + 2u * ((uint32_t)(row0 + (lane & 7) + ((lane >> 3) & 1) * 8) * QSTR
                                 + kc * 16 + ((lane >> 4) & 1) * 8);
    return ldsm_x4(addr);
}
// B-fragment pair (two 8-wide n-tiles at ntp*16, k-chunk kc) via ldmatrix.x4
__device__ __forceinline__ uint4 ldb_frag(uint32_t base, int ntp, int kc, int lane) {
    uint32_t addr = base + 2u * ((uint32_t)(ntp * 16 + ((lane >> 4) & 1) * 8 + (lane & 7)) * QSTR
                                 + kc * 16 + ((lane >> 3) & 1) * 8);
    return ldsm_x4(addr);
}

// half2 exp2: one MUFU op computes two exps (halves MUFU pressure)
__device__ __forceinline__ uint32_t ex2_h2(uint32_t h2) {
    uint32_t r;
    asm("ex2.approx.f16x2 %0, %1;" : "=r"(r) : "r"(h2));
    return r;
}

// ---------------- kernel 0: wo fp32 -> fp16 -----------------------------------
__global__ void convert_wo_kernel(const float* __restrict__ wo) {
    int i = (blockIdx.x * 256 + threadIdx.x) * 2;
    float2 f = *(const float2*)&wo[i];
    *(__half2*)&g_woh[i] = __floats2half2_rn(f.x, f.y);
}

// ---------------- kernel 1: per-head projections (HMMA) -----------------------
__device__ __forceinline__ void hmma_16x64_scalar(const __half* __restrict__ sA,
                                                  const __half* __restrict__ sB,
                                                  int warp, int g, int l, float* acc) {
    #pragma unroll
    for (int kc = 0; kc < 4; kc++) {
        uint32_t a0 = *(const uint32_t*)&sA[(warp*16+g  )*QSTR + kc*16 + 2*l    ];
        uint32_t a1 = *(const uint32_t*)&sA[(warp*16+g+8)*QSTR + kc*16 + 2*l    ];
        uint32_t a2 = *(const uint32_t*)&sA[(warp*16+g  )*QSTR + kc*16 + 2*l + 8];
        uint32_t a3 = *(const uint32_t*)&sA[(warp*16+g+8)*QSTR + kc*16 + 2*l + 8];
        #pragma unroll
        for (int nt = 0; nt < 8; nt++) {
            uint32_t b0 = *(const uint32_t*)&sB[(nt*8+g)*QSTR + kc*16 + 2*l    ];
            uint32_t b1 = *(const uint32_t*)&sB[(nt*8+g)*QSTR + kc*16 + 2*l + 8];
            mma16816(&acc[nt*4], a0, a1, a2, a3, b0, b1);
        }
    }
}

__global__ __launch_bounds__(256, 1) void proj_kernel(
        const float* __restrict__ q, const float* __restrict__ k,
        const float* __restrict__ v,
        const float* __restrict__ wq1, const float* __restrict__ wk1,
        const float* __restrict__ wq2, const float* __restrict__ wk2,
        const float* __restrict__ wv) {
    extern __shared__ __half smp[];
    __half* sX = smp;               // 3 x [128][QSTR]
    __half* sW = smp + 3*128*QSTR;  // 5 x [64][QSTR]

    const int bh = blockIdx.x, b = bh / H, h = bh % H;
    const int s0 = blockIdx.y * 128;
    const int tid = threadIdx.x;
    const int warp = tid >> 5, lane = tid & 31;
    const int g = lane >> 2, l = lane & 3;

    const float* xsrc[3] = {q, k, v};
    #pragma unroll
    for (int w = 0; w < 3; w++) {
        for (int i = tid; i < 128*32; i += 256) {
            int r = i >> 5, c = (i & 31) * 2;
            float2 f = *(const float2*)&xsrc[w][((size_t)(b*S + s0 + r))*DIM + h*HD + c];
            *(__half2*)&sX[w*128*QSTR + r*QSTR + c] = __floats2half2_rn(f.x, f.y);
        }
    }
    const float* wsrc[5] = {wq1, wk1, wq2, wk2, wv};
    #pragma unroll
    for (int w = 0; w < 5; w++) {
        const float* src = wsrc[w] + (size_t)h*HD*HD;
        for (int i = tid; i < 64*32; i += 256) {
            int r = i >> 5, c = (i & 31) * 2;
            float2 f = *(const float2*)&src[r*64 + c];
            *(__half2*)&sW[w*64*QSTR + r*QSTR + c] = __floats2half2_rn(f.x, f.y);
        }
    }
    __syncthreads();

    __half* dsts[5] = {g_q1h, g_k1h, g_q2h, g_k2h, g_vph};
    const int xsel[5] = {0, 1, 0, 1, 2};
    #pragma unroll
    for (int w = 0; w < 5; w++) {
        float acc[32];
        #pragma unroll
        for (int i = 0; i < 32; i++) acc[i] = 0.f;
        hmma_16x64_scalar(sX + xsel[w]*128*QSTR, sW + w*64*QSTR, warp, g, l, acc);
        // fold softmax scale (log2e/8) into q1 (w==0) and q2 (w==2)
        const float sc = (w == 0 || w == 2) ? QSCALE : 1.f;
        __half* dst = dsts[w] + ((size_t)bh*S + s0)*HD;
        #pragma unroll
        for (int nt = 0; nt < 8; nt++) {
            int col = nt*8 + 2*l;
            *(__half2*)&dst[(warp*16+g  )*HD + col] =
                __floats2half2_rn(acc[4*nt  ]*sc, acc[4*nt+1]*sc);
            *(__half2*)&dst[(warp*16+g+8)*HD + col] =
                __floats2half2_rn(acc[4*nt+2]*sc, acc[4*nt+3]*sc);
        }
    }
}

// ---------------- kernel 2: dual attention (HMMA, f16x2 exp) + groupnorm ------
__device__ __forceinline__ void attn_branch(uint32_t sQu, uint32_t skU, uint32_t svU,
                                            int warp, int lane,
                                            float* o, float& la, float& lb) {
    float s[32];
    #pragma unroll
    for (int i = 0; i < 32; i++) s[i] = 0.f;
    // scores: S(16x64) = Q(16x64) @ K^T
    #pragma unroll
    for (int kc = 0; kc < 4; kc++) {
        uint4 af = lda_frag(sQu, warp*16, kc, lane);
        #pragma unroll
        for (int ntp = 0; ntp < 4; ntp++) {
            uint4 bf = ldb_frag(skU, ntp, kc, lane);
            mma16816(&s[(2*ntp  )*4], af.x, af.y, af.z, af.w, bf.x, bf.y);
            mma16816(&s[(2*ntp+1)*4], af.x, af.y, af.z, af.w, bf.z, bf.w);
        }
    }
    // exp2 via ex2.approx.f16x2 (Q prescaled by log2e/8; scores bounded).
    // P is fp16 anyway, so converting s->half2 BEFORE exp costs no extra
    // precision vs the old post-exp fp16 rounding. Row sums: fp16 tree within
    // the tile (<=8 adds), unpacked to fp32 once per tile.
    uint32_t P[16];
    __half2 ha = __float2half2_rn(0.f);
    __half2 hb = ha;
    #pragma unroll
    for (int nt = 0; nt < 8; nt++) {
        __half2 h01 = __floats2half2_rn(s[4*nt  ], s[4*nt+1]);
        __half2 h23 = __floats2half2_rn(s[4*nt+2], s[4*nt+3]);
        uint32_t e01 = ex2_h2(*(uint32_t*)&h01);
        uint32_t e23 = ex2_h2(*(uint32_t*)&h23);
        ha = __hadd2(ha, *(__half2*)&e01);
        hb = __hadd2(hb, *(__half2*)&e23);
        P[2*nt]   = e01;
        P[2*nt+1] = e23;
    }
    {
        float2 fa = __half22float2(ha);
        float2 fb = __half22float2(hb);
        la += fa.x + fa.y;
        lb += fb.x + fb.y;
    }
    // o += P(16x64) @ V(64x64), V B-frags via ldmatrix.x4.trans
    #pragma unroll
    for (int kc = 0; kc < 4; kc++) {
        uint32_t a0 = P[4*kc], a1 = P[4*kc+1], a2 = P[4*kc+2], a3 = P[4*kc+3];
        #pragma unroll
        for (int ntp = 0; ntp < 4; ntp++) {
            uint32_t addr = svU + 2u * ((uint32_t)(kc*16 + (lane & 15)) * QSTR
                                        + ntp*16 + ((lane >> 4) & 1) * 8);
            uint4 bf = ldsm_x4_trans(addr);
            mma16816(&o[(2*ntp  )*4], a0, a1, a2, a3, bf.x, bf.y);
            mma16816(&o[(2*ntp+1)*4], a0, a1, a2, a3, bf.z, bf.w);
        }
    }
}

#define KV_TILE_H (64*QSTR)   // halves per K/V stage array
#define ATHR 128              // attention CTA threads
#define AQ   64               // attention q-rows per CTA

__global__ __launch_bounds__(ATHR, 3) void attn_kernel(const float* __restrict__ gain_p) {
    extern __shared__ __half smh[];
    __half* sQ1 = smh;                  // [AQ][QSTR]
    __half* sQ2 = sQ1 + AQ*QSTR;
    __half* sKV = sQ2 + AQ*QSTR;        // 2 stages x {K1,K2,V} x [64][QSTR]

    const int bh = blockIdx.x;
    const int s0 = blockIdx.y * AQ;
    const int tid = threadIdx.x;
    const int warp = tid >> 5, lane = tid & 31;
    const int g = lane >> 2, l = lane & 3;
    const size_t base = (size_t)bh * S * HD;

    for (int i = tid; i < AQ*32; i += ATHR) {
        int r = i >> 5, c = (i & 31) * 2;
        size_t gi = base + (size_t)(s0 + r)*HD + c;
        *(__half2*)&sQ1[r*QSTR+c] = *(const __half2*)&g_q1h[gi];
        *(__half2*)&sQ2[r*QSTR+c] = *(const __half2*)&g_q2h[gi];
    }

    const uint32_t skv_u = (uint32_t)__cvta_generic_to_shared(sKV);
    const uint32_t q1u = (uint32_t)__cvta_generic_to_shared(sQ1);
    const uint32_t q2u = (uint32_t)__cvta_generic_to_shared(sQ2);
    const __half* gsrc[3] = {g_k1h, g_k2h, g_vph};

    auto issue_tile = [&](int kt, int st) {
        #pragma unroll
        for (int a = 0; a < 3; a++) {
            #pragma unroll
            for (int t = 0; t < 4; t++) {
                int chunk = tid + t*ATHR;       // 512 chunks of 16B per array
                int r = chunk >> 3, c8 = (chunk & 7) * 8;
                uint32_t sa = skv_u + (uint32_t)((st*3 + a)*KV_TILE_H + r*QSTR + c8) * 2;
                cp_async16(sa, gsrc[a] + base + (size_t)(kt*64 + r)*HD + c8);
            }
        }
        cp_commit();
    };

    float o1[32], o2[32];
    #pragma unroll
    for (int i = 0; i < 32; i++) { o1[i] = 0.f; o2[i] = 0.f; }
    float l1a = 0.f, l1b = 0.f, l2a = 0.f, l2b = 0.f;

    const int KT = S/64;
    issue_tile(0, 0);
    for (int kt = 0; kt < KT; kt++) {
        const int cur = kt & 1;
        cp_wait<0>();          // tile kt arrived
        __syncthreads();       // all warps done reading stage cur^1 AND see tile kt
        if (kt + 1 < KT) issue_tile(kt+1, cur ^ 1);
        const uint32_t sk1u = skv_u + (uint32_t)((cur*3    )*KV_TILE_H)*2;
        const uint32_t sk2u = skv_u + (uint32_t)((cur*3 + 1)*KV_TILE_H)*2;
        const uint32_t svu  = skv_u + (uint32_t)((cur*3 + 2)*KV_TILE_H)*2;
        attn_branch(q1u, sk1u, svu, warp, lane, o1, l1a, l1b);
        attn_branch(q2u, sk2u, svu, warp, lane, o2, l2a, l2b);
    }

    l1a += __shfl_xor_sync(0xffffffffu, l1a, 1); l1a += __shfl_xor_sync(0xffffffffu, l1a, 2);
    l1b += __shfl_xor_sync(0xffffffffu, l1b, 1); l1b += __shfl_xor_sync(0xffffffffu, l1b, 2);
    l2a += __shfl_xor_sync(0xffffffffu, l2a, 1); l2a += __shfl_xor_sync(0xffffffffu, l2a, 2);
    l2b += __shfl_xor_sync(0xffffffffu, l2b, 1); l2b += __shfl_xor_sync(0xffffffffu, l2b, 2);

    const float gain = *gain_p;
    const float i1a = 1.f/l1a, i1b = 1.f/l1b, i2a = 1.f/l2a, i2b = 1.f/l2b;

    float va[16], vb[16];
    #pragma unroll
    for (int nt = 0; nt < 8; nt++) {
        va[2*nt]   = o1[4*nt  ]*i1a - gain*o2[4*nt  ]*i2a;
        va[2*nt+1] = o1[4*nt+1]*i1a - gain*o2[4*nt+1]*i2a;
        vb[2*nt]   = o1[4*nt+2]*i1b - gain*o2[4*nt+2]*i2b;
        vb[2*nt+1] = o1[4*nt+3]*i1b - gain*o2[4*nt+3]*i2b;
    }
    float sa = 0.f, sb = 0.f;
    #pragma unroll
    for (int i = 0; i < 16; i++) { sa += va[i]; sb += vb[i]; }
    sa += __shfl_xor_sync(0xffffffffu, sa, 1); sa += __shfl_xor_sync(0xffffffffu, sa, 2);
    sb += __shfl_xor_sync(0xffffffffu, sb, 1); sb += __shfl_xor_sync(0xffffffffu, sb, 2);
    const float ma = sa * (1.f/64.f), mb = sb * (1.f/64.f);
    float qa = 0.f, qb = 0.f;
    #pragma unroll
    for (int i = 0; i < 16; i++) {
        float da = va[i] - ma; qa += da*da;
        float db = vb[i] - mb; qb += db*db;
    }
    qa += __shfl_xor_sync(0xffffffffu, qa, 1); qa += __shfl_xor_sync(0xffffffffu, qa, 2);
    qb += __shfl_xor_sync(0xffffffffu, qb, 1); qb += __shfl_xor_sync(0xffffffffu, qb, 2);
    const float ra = rsqrtf(qa*(1.f/64.f) + EPS);
    const float rb = rsqrtf(qb*(1.f/64.f) + EPS);

    const int b = bh / H, h = bh % H;
    const size_t rowA = (size_t)(b*S + s0 + warp*16 + g)*DIM + h*HD;
    const size_t rowB = rowA + (size_t)8*DIM;
    #pragma unroll
    for (int nt = 0; nt < 8; nt++) {
        int col = nt*8 + 2*l;
        *(__half2*)&g_aoh[rowA + col] = __floats2half2_rn((va[2*nt]-ma)*ra, (va[2*nt+1]-ma)*ra);
        *(__half2*)&g_aoh[rowB + col] = __floats2half2_rn((vb[2*nt]-mb)*rb, (vb[2*nt+1]-mb)*rb);
    }
}

// ---------------- kernel 3: out = ao @ wo^T (HMMA, 3-stage cp.async) ----------
#define OG_STAGE_H (2*128*QSTR)  // halves per stage (A tile + W tile)
#define OG_NSTAGE 3

__global__ __launch_bounds__(256, 1) void out_gemm_kernel(float* __restrict__ out) {
    extern __shared__ __half smg[];
    const int n0 = blockIdx.x * 128;
    const int e0 = blockIdx.y * 128;
    const int tid = threadIdx.x;
    const int warp = tid >> 5, lane = tid & 31;
    const int g = lane >> 2, l = lane & 3;
    const uint32_t smg_u = (uint32_t)__cvta_generic_to_shared(smg);

    auto issue_tile = [&](int kt, int st) {
        #pragma unroll
        for (int t = 0; t < 4; t++) {            // A: 1024 chunks of 16B
            int chunk = tid + t*256;
            int r = chunk >> 3, c8 = (chunk & 7) * 8;
            uint32_t sa = smg_u + (uint32_t)(st*OG_STAGE_H + r*QSTR + c8) * 2;
            cp_async16(sa, &g_aoh[(size_t)(n0+r)*DIM + kt*64 + c8]);
        }
        #pragma unroll
        for (int t = 0; t < 4; t++) {            // W
            int chunk = tid + t*256;
            int r = chunk >> 3, c8 = (chunk & 7) * 8;
            uint32_t sa = smg_u + (uint32_t)(st*OG_STAGE_H + 128*QSTR + r*QSTR + c8) * 2;
            cp_async16(sa, &g_woh[(size_t)(e0+r)*DIM + kt*64 + c8]);
        }
        cp_commit();
    };

    float acc[64];
    #pragma unroll
    for (int i = 0; i < 64; i++) acc[i] = 0.f;

    const int KT = DIM/64;
    issue_tile(0, 0);
    for (int kt = 0; kt < KT; kt++) {
        const int cur = kt & 1;
        cp_wait<0>();
        __syncthreads();                          // tile kt visible; other stage free
        if (kt + 1 < KT) issue_tile(kt + 1, cur ^ 1);
        const uint32_t sAu = smg_u + (uint32_t)(cur*OG_STAGE_H)*2;
        const uint32_t sWu = sAu + (uint32_t)(128*QSTR)*2;
        #pragma unroll
        for (int kc = 0; kc < 4; kc++) {
            uint4 af = lda_frag(sAu, warp*16, kc, lane);
            #pragma unroll
            for (int ntp = 0; ntp < 8; ntp++) {
                uint4 bf = ldb_frag(sWu, ntp, kc, lane);
                mma16816(&acc[(2*ntp  )*4], af.x, af.y, af.z, af.w, bf.x, bf.y);
                mma16816(&acc[(2*ntp+1)*4], af.x, af.y, af.z, af.w, bf.z, bf.w);
            }
        }
    }
    #pragma unroll
    for (int nt = 0; nt < 16; nt++) {
        *(float2*)&out[(size_t)(n0+warp*16+g  )*DIM + e0 + nt*8 + 2*l] =
            make_float2(acc[4*nt], acc[4*nt+1]);
        *(float2*)&out[(size_t)(n0+warp*16+g+8)*DIM + e0 + nt*8 + 2*l] =
            make_float2(acc[4*nt+2], acc[4*nt+3]);
    }
}

// ---------------- launch ------------------------------------------------------
extern "C" void kernel_launch(void* const* d_in, const int* in_sizes, int n_in,
                              void* d_out, int out_size) {
    const float* q    = (const float*)d_in[0];
    const float* k    = (const float*)d_in[1];
    const float* v    = (const float*)d_in[2];
    const float* wq1  = (const float*)d_in[3];
    const float* wk1  = (const float*)d_in[4];
    const float* wq2  = (const float*)d_in[5];
    const float* wk2  = (const float*)d_in[6];
    const float* wv   = (const float*)d_in[7];
    const float* wo   = (const float*)d_in[8];
    const float* gain = (const float*)d_in[9];
    float* out = (float*)d_out;

    const int smem_proj = (int)((3*128 + 5*64) * QSTR * sizeof(__half));          // 101376
    const int smem_attn = (int)((2*AQ*QSTR + 6*KV_TILE_H) * sizeof(__half));      // 73728
    const int smem_gemm = (int)((2*OG_STAGE_H) * sizeof(__half));                 // 73728
    static bool attr_done = false;
    if (!attr_done) {
        cudaFuncSetAttribute(proj_kernel, cudaFuncAttributeMaxDynamicSharedMemorySize, smem_proj);
        cudaFuncSetAttribute(attn_kernel, cudaFuncAttributeMaxDynamicSharedMemorySize, smem_attn);
        cudaFuncSetAttribute(out_gemm_kernel, cudaFuncAttributeMaxDynamicSharedMemorySize, smem_gemm);
        attr_done = true;
    }

    convert_wo_kernel<<<DIM*DIM/512, 256>>>(wo);

    dim3 gp(B*H, S/128);
    proj_kernel<<<gp, 256, smem_proj>>>(q, k, v, wq1, wk1, wq2, wk2, wv);

    dim3 ga(B*H, S/AQ);
    attn_kernel<<<ga, ATHR, smem_attn>>>(gain);

    dim3 gg(B*S/128, DIM/128);
    out_gemm_kernel<<<gg, 256, smem_gemm>>>(out);
}

// round 15
// speedup vs baseline: 1.1117x; 1.0067x over previous
#include <cuda_runtime.h>
#include <cuda_fp16.h>
#include <cstdint>

#define B   2
#define S   2048
#define H   16
#define HD  64
#define DIM 1024
#define EPS 1e-5f
#define QSTR 72         // half smem row stride (conflict-free for ldmatrix + mma frags)
#define QSCALE 0.180336879f   // log2(e)/8 folded into q1/q2 at projection time

// ---------------- scratch (device globals; allocation-free rule) -------------
__device__ __align__(16) __half g_q1h[(size_t)B*H*S*HD];
__device__ __align__(16) __half g_k1h[(size_t)B*H*S*HD];
__device__ __align__(16) __half g_q2h[(size_t)B*H*S*HD];
__device__ __align__(16) __half g_k2h[(size_t)B*H*S*HD];
__device__ __align__(16) __half g_vph[(size_t)B*H*S*HD];
__device__ __align__(16) __half g_aoh[(size_t)B*S*DIM];
__device__ __align__(16) __half g_woh[(size_t)DIM*DIM];

// ---------------- asm helpers -------------------------------------------------
__device__ __forceinline__ void mma16816(float* d, uint32_t a0, uint32_t a1,
                                         uint32_t a2, uint32_t a3,
                                         uint32_t b0, uint32_t b1) {
    asm volatile(
        "mma.sync.aligned.m16n8k16.row.col.f32.f16.f16.f32 "
        "{%0,%1,%2,%3}, {%4,%5,%6,%7}, {%8,%9}, {%0,%1,%2,%3};\n"
        : "+f"(d[0]), "+f"(d[1]), "+f"(d[2]), "+f"(d[3])
        : "r"(a0), "r"(a1), "r"(a2), "r"(a3), "r"(b0), "r"(b1));
}

__device__ __forceinline__ uint4 ldsm_x4(uint32_t addr) {
    uint4 r;
    asm volatile("ldmatrix.sync.aligned.m8n8.x4.shared.b16 {%0,%1,%2,%3}, [%4];"
                 : "=r"(r.x), "=r"(r.y), "=r"(r.z), "=r"(r.w) : "r"(addr));
    return r;
}
__device__ __forceinline__ uint4 ldsm_x4_trans(uint32_t addr) {
    uint4 r;
    asm volatile("ldmatrix.sync.aligned.m8n8.x4.trans.shared.b16 {%0,%1,%2,%3}, [%4];"
                 : "=r"(r.x), "=r"(r.y), "=r"(r.z), "=r"(r.w) : "r"(addr));
    return r;
}

__device__ __forceinline__ void cp_async16(uint32_t saddr, const void* gptr) {
    asm volatile("cp.async.cg.shared.global [%0], [%1], 16;\n"
                 :: "r"(saddr), "l"(gptr));
}
__device__ __forceinline__ void cp_commit() {
    asm volatile("cp.async.commit_group;\n");
}
template <int N> __device__ __forceinline__ void cp_wait() {
    asm volatile("cp.async.wait_group %0;\n" :: "n"(N));
}

// A-fragment (16x16 tile at row0, k-chunk kc) via ldmatrix.x4
__device__ __forceinline__ uint4 lda_frag(uint32_t base, int row0, int kc, int lane) {
    uint32_t addr = base + 2u * ((uint32_t)(row0 + (lane & 7) + ((lane >> 3) & 1) * 8) * QSTR
                                 + kc * 16 + ((lane >> 4) & 1) * 8);
    return ldsm_x4(addr);
}
// B-fragment pair (two 8-wide n-tiles at ntp*16, k-chunk kc) via ldmatrix.x4
__device__ __forceinline__ uint4 ldb_frag(uint32_t base, int ntp, int kc, int lane) {
    uint32_t addr = base + 2u * ((uint32_t)(ntp * 16 + ((lane >> 4) & 1) * 8 + (lane & 7)) * QSTR
                                 + kc * 16 + ((lane >> 3) & 1) * 8);
    return ldsm_x4(addr);
}

// half2 exp2: one MUFU op computes two exps (halves MUFU pressure)
__device__ __forceinline__ uint32_t ex2_h2(uint32_t h2) {
    uint32_t r;
    asm("ex2.approx.f16x2 %0, %1;" : "=r"(r) : "r"(h2));
    return r;
}

// ---------------- kernel 0: wo fp32 -> fp16 -----------------------------------
__global__ void convert_wo_kernel(const float* __restrict__ wo) {
    int i = (blockIdx.x * 256 + threadIdx.x) * 2;
    float2 f = *(const float2*)&wo[i];
    *(__half2*)&g_woh[i] = __floats2half2_rn(f.x, f.y);
}

// ---------------- kernel 1: per-head projections (HMMA) -----------------------
__device__ __forceinline__ void hmma_16x64_scalar(const __half* __restrict__ sA,
                                                  const __half* __restrict__ sB,
                                                  int warp, int g, int l, float* acc) {
    #pragma unroll
    for (int kc = 0; kc < 4; kc++) {
        uint32_t a0 = *(const uint32_t*)&sA[(warp*16+g  )*QSTR + kc*16 + 2*l    ];
        uint32_t a1 = *(const uint32_t*)&sA[(warp*16+g+8)*QSTR + kc*16 + 2*l    ];
        uint32_t a2 = *(const uint32_t*)&sA[(warp*16+g  )*QSTR + kc*16 + 2*l + 8];
        uint32_t a3 = *(const uint32_t*)&sA[(warp*16+g+8)*QSTR + kc*16 + 2*l + 8];
        #pragma unroll
        for (int nt = 0; nt < 8; nt++) {
            uint32_t b0 = *(const uint32_t*)&sB[(nt*8+g)*QSTR + kc*16 + 2*l    ];
            uint32_t b1 = *(const uint32_t*)&sB[(nt*8+g)*QSTR + kc*16 + 2*l + 8];
            mma16816(&acc[nt*4], a0, a1, a2, a3, b0, b1);
        }
    }
}

__global__ __launch_bounds__(256, 1) void proj_kernel(
        const float* __restrict__ q, const float* __restrict__ k,
        const float* __restrict__ v,
        const float* __restrict__ wq1, const float* __restrict__ wk1,
        const float* __restrict__ wq2, const float* __restrict__ wk2,
        const float* __restrict__ wv) {
    extern __shared__ __half smp[];
    __half* sX = smp;               // 3 x [128][QSTR]
    __half* sW = smp + 3*128*QSTR;  // 5 x [64][QSTR]

    const int bh = blockIdx.x, b = bh / H, h = bh % H;
    const int s0 = blockIdx.y * 128;
    const int tid = threadIdx.x;
    const int warp = tid >> 5, lane = tid & 31;
    const int g = lane >> 2, l = lane & 3;

    const float* xsrc[3] = {q, k, v};
    #pragma unroll
    for (int w = 0; w < 3; w++) {
        for (int i = tid; i < 128*32; i += 256) {
            int r = i >> 5, c = (i & 31) * 2;
            float2 f = *(const float2*)&xsrc[w][((size_t)(b*S + s0 + r))*DIM + h*HD + c];
            *(__half2*)&sX[w*128*QSTR + r*QSTR + c] = __floats2half2_rn(f.x, f.y);
        }
    }
    const float* wsrc[5] = {wq1, wk1, wq2, wk2, wv};
    #pragma unroll
    for (int w = 0; w < 5; w++) {
        const float* src = wsrc[w] + (size_t)h*HD*HD;
        for (int i = tid; i < 64*32; i += 256) {
            int r = i >> 5, c = (i & 31) * 2;
            float2 f = *(const float2*)&src[r*64 + c];
            *(__half2*)&sW[w*64*QSTR + r*QSTR + c] = __floats2half2_rn(f.x, f.y);
        }
    }
    __syncthreads();

    __half* dsts[5] = {g_q1h, g_k1h, g_q2h, g_k2h, g_vph};
    const int xsel[5] = {0, 1, 0, 1, 2};
    #pragma unroll
    for (int w = 0; w < 5; w++) {
        float acc[32];
        #pragma unroll
        for (int i = 0; i < 32; i++) acc[i] = 0.f;
        hmma_16x64_scalar(sX + xsel[w]*128*QSTR, sW + w*64*QSTR, warp, g, l, acc);
        // fold softmax scale (log2e/8) into q1 (w==0) and q2 (w==2)
        const float sc = (w == 0 || w == 2) ? QSCALE : 1.f;
        __half* dst = dsts[w] + ((size_t)bh*S + s0)*HD;
        #pragma unroll
        for (int nt = 0; nt < 8; nt++) {
            int col = nt*8 + 2*l;
            *(__half2*)&dst[(warp*16+g  )*HD + col] =
                __floats2half2_rn(acc[4*nt  ]*sc, acc[4*nt+1]*sc);
            *(__half2*)&dst[(warp*16+g+8)*HD + col] =
                __floats2half2_rn(acc[4*nt+2]*sc, acc[4*nt+3]*sc);
        }
    }
}

// ---------------- kernel 2: dual attention (HMMA, f16x2 exp) + groupnorm ------
__device__ __forceinline__ void attn_branch(uint32_t sQu, uint32_t skU, uint32_t svU,
                                            int warp, int lane,
                                            float* o, float& la, float& lb) {
    float s[32];
    #pragma unroll
    for (int i = 0; i < 32; i++) s[i] = 0.f;
    // scores: S(16x64) = Q(16x64) @ K^T
    #pragma unroll
    for (int kc = 0; kc < 4; kc++) {
        uint4 af = lda_frag(sQu, warp*16, kc, lane);
        #pragma unroll
        for (int ntp = 0; ntp < 4; ntp++) {
            uint4 bf = ldb_frag(skU, ntp, kc, lane);
            mma16816(&s[(2*ntp  )*4], af.x, af.y, af.z, af.w, bf.x, bf.y);
            mma16816(&s[(2*ntp+1)*4], af.x, af.y, af.z, af.w, bf.z, bf.w);
        }
    }
    // exp2 via ex2.approx.f16x2 (Q prescaled by log2e/8; scores bounded).
    uint32_t P[16];
    __half2 ha = __float2half2_rn(0.f);
    __half2 hb = ha;
    #pragma unroll
    for (int nt = 0; nt < 8; nt++) {
        __half2 h01 = __floats2half2_rn(s[4*nt  ], s[4*nt+1]);
        __half2 h23 = __floats2half2_rn(s[4*nt+2], s[4*nt+3]);
        uint32_t e01 = ex2_h2(*(uint32_t*)&h01);
        uint32_t e23 = ex2_h2(*(uint32_t*)&h23);
        ha = __hadd2(ha, *(__half2*)&e01);
        hb = __hadd2(hb, *(__half2*)&e23);
        P[2*nt]   = e01;
        P[2*nt+1] = e23;
    }
    {
        float2 fa = __half22float2(ha);
        float2 fb = __half22float2(hb);
        la += fa.x + fa.y;
        lb += fb.x + fb.y;
    }
    // o += P(16x64) @ V(64x64), V B-frags via ldmatrix.x4.trans
    #pragma unroll
    for (int kc = 0; kc < 4; kc++) {
        uint32_t a0 = P[4*kc], a1 = P[4*kc+1], a2 = P[4*kc+2], a3 = P[4*kc+3];
        #pragma unroll
        for (int ntp = 0; ntp < 4; ntp++) {
            uint32_t addr = svU + 2u * ((uint32_t)(kc*16 + (lane & 15)) * QSTR
                                        + ntp*16 + ((lane >> 4) & 1) * 8);
            uint4 bf = ldsm_x4_trans(addr);
            mma16816(&o[(2*ntp  )*4], a0, a1, a2, a3, bf.x, bf.y);
            mma16816(&o[(2*ntp+1)*4], a0, a1, a2, a3, bf.z, bf.w);
        }
    }
}

#define KV_TILE_H (64*QSTR)   // halves per K/V stage array
#define ATHR 128              // attention CTA threads
#define AQ   64               // attention q-rows per CTA

__global__ __launch_bounds__(ATHR, 3) void attn_kernel(const float* __restrict__ gain_p) {
    extern __shared__ __half smh[];
    __half* sQ1 = smh;                  // [AQ][QSTR]
    __half* sQ2 = sQ1 + AQ*QSTR;
    __half* sKV = sQ2 + AQ*QSTR;        // 2 stages x {K1,K2,V} x [64][QSTR]

    const int bh = blockIdx.x;
    const int s0 = blockIdx.y * AQ;
    const int tid = threadIdx.x;
    const int warp = tid >> 5, lane = tid & 31;
    const int g = lane >> 2, l = lane & 3;
    const size_t base = (size_t)bh * S * HD;

    for (int i = tid; i < AQ*32; i += ATHR) {
        int r = i >> 5, c = (i & 31) * 2;
        size_t gi = base + (size_t)(s0 + r)*HD + c;
        *(__half2*)&sQ1[r*QSTR+c] = *(const __half2*)&g_q1h[gi];
        *(__half2*)&sQ2[r*QSTR+c] = *(const __half2*)&g_q2h[gi];
    }

    const uint32_t skv_u = (uint32_t)__cvta_generic_to_shared(sKV);
    const uint32_t q1u = (uint32_t)__cvta_generic_to_shared(sQ1);
    const uint32_t q2u = (uint32_t)__cvta_generic_to_shared(sQ2);
    const __half* gsrc[3] = {g_k1h, g_k2h, g_vph};

    auto issue_tile = [&](int kt, int st) {
        #pragma unroll
        for (int a = 0; a < 3; a++) {
            #pragma unroll
            for (int t = 0; t < 4; t++) {
                int chunk = tid + t*ATHR;       // 512 chunks of 16B per array
                int r = chunk >> 3, c8 = (chunk & 7) * 8;
                uint32_t sa = skv_u + (uint32_t)((st*3 + a)*KV_TILE_H + r*QSTR + c8) * 2;
                cp_async16(sa, gsrc[a] + base + (size_t)(kt*64 + r)*HD + c8);
            }
        }
        cp_commit();
    };

    float o1[32], o2[32];
    #pragma unroll
    for (int i = 0; i < 32; i++) { o1[i] = 0.f; o2[i] = 0.f; }
    float l1a = 0.f, l1b = 0.f, l2a = 0.f, l2b = 0.f;

    const int KT = S/64;
    issue_tile(0, 0);
    for (int kt = 0; kt < KT; kt++) {
        const int cur = kt & 1;
        cp_wait<0>();          // tile kt arrived
        __syncthreads();       // all warps done reading stage cur^1 AND see tile kt
        if (kt + 1 < KT) issue_tile(kt+1, cur ^ 1);
        const uint32_t sk1u = skv_u + (uint32_t)((cur*3    )*KV_TILE_H)*2;
        const uint32_t sk2u = skv_u + (uint32_t)((cur*3 + 1)*KV_TILE_H)*2;
        const uint32_t svu  = skv_u + (uint32_t)((cur*3 + 2)*KV_TILE_H)*2;
        attn_branch(q1u, sk1u, svu, warp, lane, o1, l1a, l1b);
        attn_branch(q2u, sk2u, svu, warp, lane, o2, l2a, l2b);
    }

    l1a += __shfl_xor_sync(0xffffffffu, l1a, 1); l1a += __shfl_xor_sync(0xffffffffu, l1a, 2);
    l1b += __shfl_xor_sync(0xffffffffu, l1b, 1); l1b += __shfl_xor_sync(0xffffffffu, l1b, 2);
    l2a += __shfl_xor_sync(0xffffffffu, l2a, 1); l2a += __shfl_xor_sync(0xffffffffu, l2a, 2);
    l2b += __shfl_xor_sync(0xffffffffu, l2b, 1); l2b += __shfl_xor_sync(0xffffffffu, l2b, 2);

    const float gain = *gain_p;
    const float i1a = 1.f/l1a, i1b = 1.f/l1b, i2a = 1.f/l2a, i2b = 1.f/l2b;

    float va[16], vb[16];
    #pragma unroll
    for (int nt = 0; nt < 8; nt++) {
        va[2*nt]   = o1[4*nt  ]*i1a - gain*o2[4*nt  ]*i2a;
        va[2*nt+1] = o1[4*nt+1]*i1a - gain*o2[4*nt+1]*i2a;
        vb[2*nt]   = o1[4*nt+2]*i1b - gain*o2[4*nt+2]*i2b;
        vb[2*nt+1] = o1[4*nt+3]*i1b - gain*o2[4*nt+3]*i2b;
    }
    float sa = 0.f, sb = 0.f;
    #pragma unroll
    for (int i = 0; i < 16; i++) { sa += va[i]; sb += vb[i]; }
    sa += __shfl_xor_sync(0xffffffffu, sa, 1); sa += __shfl_xor_sync(0xffffffffu, sa, 2);
    sb += __shfl_xor_sync(0xffffffffu, sb, 1); sb += __shfl_xor_sync(0xffffffffu, sb, 2);
    const float ma = sa * (1.f/64.f), mb = sb * (1.f/64.f);
    float qa = 0.f, qb = 0.f;
    #pragma unroll
    for (int i = 0; i < 16; i++) {
        float da = va[i] - ma; qa += da*da;
        float db = vb[i] - mb; qb += db*db;
    }
    qa += __shfl_xor_sync(0xffffffffu, qa, 1); qa += __shfl_xor_sync(0xffffffffu, qa, 2);
    qb += __shfl_xor_sync(0xffffffffu, qb, 1); qb += __shfl_xor_sync(0xffffffffu, qb, 2);
    const float ra = rsqrtf(qa*(1.f/64.f) + EPS);
    const float rb = rsqrtf(qb*(1.f/64.f) + EPS);

    const int b = bh / H, h = bh % H;
    const size_t rowA = (size_t)(b*S + s0 + warp*16 + g)*DIM + h*HD;
    const size_t rowB = rowA + (size_t)8*DIM;
    #pragma unroll
    for (int nt = 0; nt < 8; nt++) {
        int col = nt*8 + 2*l;
        *(__half2*)&g_aoh[rowA + col] = __floats2half2_rn((va[2*nt]-ma)*ra, (va[2*nt+1]-ma)*ra);
        *(__half2*)&g_aoh[rowB + col] = __floats2half2_rn((vb[2*nt]-mb)*rb, (vb[2*nt+1]-mb)*rb);
    }
}

// ---------------- kernel 3: out = ao @ wo^T (HMMA, 128thr, 128x64 tile) -------
// N-split small-CTA (R9 pattern along N): 128 threads, each warp 32 rows x 64
// cols (same acc[64]/regs as before) -> 3 CTAs/SM. A traffic rises (L2 has
// headroom); W per-CTA stripe halves.
#define OG_STAGE_H ((128+64)*QSTR)  // halves per stage (A 128 rows + W 64 rows)

__global__ __launch_bounds__(128, 3) void out_gemm_kernel(float* __restrict__ out) {
    extern __shared__ __half smg[];
    const int n0 = blockIdx.x * 128;
    const int e0 = blockIdx.y * 64;
    const int tid = threadIdx.x;
    const int warp = tid >> 5, lane = tid & 31;
    const int g = lane >> 2, l = lane & 3;
    const uint32_t smg_u = (uint32_t)__cvta_generic_to_shared(smg);

    auto issue_tile = [&](int kt, int st) {
        #pragma unroll
        for (int t = 0; t < 8; t++) {            // A: 128 rows -> 1024 chunks of 16B
            int chunk = tid + t*128;
            int r = chunk >> 3, c8 = (chunk & 7) * 8;
            uint32_t sa = smg_u + (uint32_t)(st*OG_STAGE_H + r*QSTR + c8) * 2;
            cp_async16(sa, &g_aoh[(size_t)(n0+r)*DIM + kt*64 + c8]);
        }
        #pragma unroll
        for (int t = 0; t < 4; t++) {            // W: 64 rows -> 512 chunks
            int chunk = tid + t*128;
            int r = chunk >> 3, c8 = (chunk & 7) * 8;
            uint32_t sa = smg_u + (uint32_t)(st*OG_STAGE_H + 128*QSTR + r*QSTR + c8) * 2;
            cp_async16(sa, &g_woh[(size_t)(e0+r)*DIM + kt*64 + c8]);
        }
        cp_commit();
    };

    float acc[64];
    #pragma unroll
    for (int i = 0; i < 64; i++) acc[i] = 0.f;

    const int KT = DIM/64;
    issue_tile(0, 0);
    for (int kt = 0; kt < KT; kt++) {
        const int cur = kt & 1;
        cp_wait<0>();
        __syncthreads();                          // tile kt visible; other stage free
        if (kt + 1 < KT) issue_tile(kt + 1, cur ^ 1);
        const uint32_t sAu = smg_u + (uint32_t)(cur*OG_STAGE_H)*2;
        const uint32_t sWu = sAu + (uint32_t)(128*QSTR)*2;
        #pragma unroll
        for (int kc = 0; kc < 4; kc++) {
            uint4 af0 = lda_frag(sAu, warp*32,      kc, lane);
            uint4 af1 = lda_frag(sAu, warp*32 + 16, kc, lane);
            #pragma unroll
            for (int ntp = 0; ntp < 4; ntp++) {
                uint4 bf = ldb_frag(sWu, ntp, kc, lane);
                mma16816(&acc[(2*ntp  )*4],      af0.x, af0.y, af0.z, af0.w, bf.x, bf.y);
                mma16816(&acc[(2*ntp+1)*4],      af0.x, af0.y, af0.z, af0.w, bf.z, bf.w);
                mma16816(&acc[(8 + 2*ntp  )*4],  af1.x, af1.y, af1.z, af1.w, bf.x, bf.y);
                mma16816(&acc[(8 + 2*ntp+1)*4],  af1.x, af1.y, af1.z, af1.w, bf.z, bf.w);
            }
        }
    }
    #pragma unroll
    for (int rt = 0; rt < 2; rt++) {
        #pragma unroll
        for (int nt = 0; nt < 8; nt++) {
            const float* a4 = &acc[(rt*8 + nt)*4];
            *(float2*)&out[(size_t)(n0+warp*32+rt*16+g  )*DIM + e0 + nt*8 + 2*l] =
                make_float2(a4[0], a4[1]);
            *(float2*)&out[(size_t)(n0+warp*32+rt*16+g+8)*DIM + e0 + nt*8 + 2*l] =
                make_float2(a4[2], a4[3]);
        }
    }
}

// ---------------- launch ------------------------------------------------------
extern "C" void kernel_launch(void* const* d_in, const int* in_sizes, int n_in,
                              void* d_out, int out_size) {
    const float* q    = (const float*)d_in[0];
    const float* k    = (const float*)d_in[1];
    const float* v    = (const float*)d_in[2];
    const float* wq1  = (const float*)d_in[3];
    const float* wk1  = (const float*)d_in[4];
    const float* wq2  = (const float*)d_in[5];
    const float* wk2  = (const float*)d_in[6];
    const float* wv   = (const float*)d_in[7];
    const float* wo   = (const float*)d_in[8];
    const float* gain = (const float*)d_in[9];
    float* out = (float*)d_out;

    const int smem_proj = (int)((3*128 + 5*64) * QSTR * sizeof(__half));          // 101376
    const int smem_attn = (int)((2*AQ*QSTR + 6*KV_TILE_H) * sizeof(__half));      // 73728
    const int smem_gemm = (int)((2*OG_STAGE_H) * sizeof(__half));                 // 55296
    static bool attr_done = false;
    if (!attr_done) {
        cudaFuncSetAttribute(proj_kernel, cudaFuncAttributeMaxDynamicSharedMemorySize, smem_proj);
        cudaFuncSetAttribute(attn_kernel, cudaFuncAttributeMaxDynamicSharedMemorySize, smem_attn);
        cudaFuncSetAttribute(out_gemm_kernel, cudaFuncAttributeMaxDynamicSharedMemorySize, smem_gemm);
        attr_done = true;
    }

    convert_wo_kernel<<<DIM*DIM/512, 256>>>(wo);

    dim3 gp(B*H, S/128);
    proj_kernel<<<gp, 256, smem_proj>>>(q, k, v, wq1, wk1, wq2, wk2, wv);

    dim3 ga(B*H, S/AQ);
    attn_kernel<<<ga, ATHR, smem_attn>>>(gain);

    dim3 gg(B*S/128, DIM/64);
    out_gemm_kernel<<<gg, 128, smem_gemm>>>(out);
}

// round 16
// speedup vs baseline: 1.1326x; 1.0188x over previous
#include <cuda_runtime.h>
#include <cuda_fp16.h>
#include <cstdint>

#define B   2
#define S   2048
#define H   16
#define HD  64
#define DIM 1024
#define EPS 1e-5f
#define QSTR 72         // half smem row stride (conflict-free for ldmatrix + mma frags)
#define QSCALE 0.180336879f   // log2(e)/8 folded into q1/q2 at projection time

// ---------------- scratch (device globals; allocation-free rule) -------------
__device__ __align__(16) __half g_q1h[(size_t)B*H*S*HD];
__device__ __align__(16) __half g_k1h[(size_t)B*H*S*HD];
__device__ __align__(16) __half g_q2h[(size_t)B*H*S*HD];
__device__ __align__(16) __half g_k2h[(size_t)B*H*S*HD];
__device__ __align__(16) __half g_vph[(size_t)B*H*S*HD];
__device__ __align__(16) __half g_aoh[(size_t)B*S*DIM];
__device__ __align__(16) __half g_woh[(size_t)DIM*DIM];

// ---------------- asm helpers -------------------------------------------------
__device__ __forceinline__ void mma16816(float* d, uint32_t a0, uint32_t a1,
                                         uint32_t a2, uint32_t a3,
                                         uint32_t b0, uint32_t b1) {
    asm volatile(
        "mma.sync.aligned.m16n8k16.row.col.f32.f16.f16.f32 "
        "{%0,%1,%2,%3}, {%4,%5,%6,%7}, {%8,%9}, {%0,%1,%2,%3};\n"
        : "+f"(d[0]), "+f"(d[1]), "+f"(d[2]), "+f"(d[3])
        : "r"(a0), "r"(a1), "r"(a2), "r"(a3), "r"(b0), "r"(b1));
}

__device__ __forceinline__ uint4 ldsm_x4(uint32_t addr) {
    uint4 r;
    asm volatile("ldmatrix.sync.aligned.m8n8.x4.shared.b16 {%0,%1,%2,%3}, [%4];"
                 : "=r"(r.x), "=r"(r.y), "=r"(r.z), "=r"(r.w) : "r"(addr));
    return r;
}
__device__ __forceinline__ uint4 ldsm_x4_trans(uint32_t addr) {
    uint4 r;
    asm volatile("ldmatrix.sync.aligned.m8n8.x4.trans.shared.b16 {%0,%1,%2,%3}, [%4];"
                 : "=r"(r.x), "=r"(r.y), "=r"(r.z), "=r"(r.w) : "r"(addr));
    return r;
}

__device__ __forceinline__ void cp_async16(uint32_t saddr, const void* gptr) {
    asm volatile("cp.async.cg.shared.global [%0], [%1], 16;\n"
                 :: "r"(saddr), "l"(gptr));
}
__device__ __forceinline__ void cp_commit() {
    asm volatile("cp.async.commit_group;\n");
}
template <int N> __device__ __forceinline__ void cp_wait() {
    asm volatile("cp.async.wait_group %0;\n" :: "n"(N));
}

// A-fragment (16x16 tile at row0, k-chunk kc) via ldmatrix.x4
__device__ __forceinline__ uint4 lda_frag(uint32_t base, int row0, int kc, int lane) {
    uint32_t addr = base + 2u * ((uint32_t)(row0 + (lane & 7) + ((lane >> 3) & 1) * 8) * QSTR
                                 + kc * 16 + ((lane >> 4) & 1) * 8);
    return ldsm_x4(addr);
}
// B-fragment pair (two 8-wide n-tiles at ntp*16, k-chunk kc) via ldmatrix.x4
__device__ __forceinline__ uint4 ldb_frag(uint32_t base, int ntp, int kc, int lane) {
    uint32_t addr = base + 2u * ((uint32_t)(ntp * 16 + ((lane >> 4) & 1) * 8 + (lane & 7)) * QSTR
                                 + kc * 16 + ((lane >> 3) & 1) * 8);
    return ldsm_x4(addr);
}

// half2 exp2: one MUFU op computes two exps (halves MUFU pressure)
__device__ __forceinline__ uint32_t ex2_h2(uint32_t h2) {
    uint32_t r;
    asm("ex2.approx.f16x2 %0, %1;" : "=r"(r) : "r"(h2));
    return r;
}

// ---------------- kernel 1: per-head projections (HMMA, ldsm) + wo convert ----
__global__ __launch_bounds__(256, 1) void proj_kernel(
        const float* __restrict__ q, const float* __restrict__ k,
        const float* __restrict__ v,
        const float* __restrict__ wq1, const float* __restrict__ wk1,
        const float* __restrict__ wq2, const float* __restrict__ wk2,
        const float* __restrict__ wv,  const float* __restrict__ wo) {
    extern __shared__ __half smp[];
    __half* sX = smp;               // 3 x [128][QSTR]
    __half* sW = smp + 3*128*QSTR;  // 5 x [64][QSTR]

    const int bh = blockIdx.x, b = bh / H, h = bh % H;
    const int s0 = blockIdx.y * 128;
    const int tid = threadIdx.x;
    const int warp = tid >> 5, lane = tid & 31;
    const int g = lane >> 2, l = lane & 3;

    const float* xsrc[3] = {q, k, v};
    #pragma unroll
    for (int w = 0; w < 3; w++) {
        for (int i = tid; i < 128*32; i += 256) {
            int r = i >> 5, c = (i & 31) * 2;
            float2 f = *(const float2*)&xsrc[w][((size_t)(b*S + s0 + r))*DIM + h*HD + c];
            *(__half2*)&sX[w*128*QSTR + r*QSTR + c] = __floats2half2_rn(f.x, f.y);
        }
    }
    const float* wsrc[5] = {wq1, wk1, wq2, wk2, wv};
    #pragma unroll
    for (int w = 0; w < 5; w++) {
        const float* src = wsrc[w] + (size_t)h*HD*HD;
        for (int i = tid; i < 64*32; i += 256) {
            int r = i >> 5, c = (i & 31) * 2;
            float2 f = *(const float2*)&src[r*64 + c];
            *(__half2*)&sW[w*64*QSTR + r*QSTR + c] = __floats2half2_rn(f.x, f.y);
        }
    }
    __syncthreads();

    const uint32_t sXu = (uint32_t)__cvta_generic_to_shared(sX);
    const uint32_t sWu = (uint32_t)__cvta_generic_to_shared(sW);
    __half* dsts[5] = {g_q1h, g_k1h, g_q2h, g_k2h, g_vph};
    const int xsel[5] = {0, 1, 0, 1, 2};
    #pragma unroll
    for (int w = 0; w < 5; w++) {
        float acc[32];
        #pragma unroll
        for (int i = 0; i < 32; i++) acc[i] = 0.f;
        const uint32_t xu = sXu + (uint32_t)(xsel[w]*128*QSTR)*2;
        const uint32_t wu = sWu + (uint32_t)(w*64*QSTR)*2;
        #pragma unroll
        for (int kc = 0; kc < 4; kc++) {
            uint4 af = lda_frag(xu, warp*16, kc, lane);
            #pragma unroll
            for (int ntp = 0; ntp < 4; ntp++) {
                uint4 bf = ldb_frag(wu, ntp, kc, lane);
                mma16816(&acc[(2*ntp  )*4], af.x, af.y, af.z, af.w, bf.x, bf.y);
                mma16816(&acc[(2*ntp+1)*4], af.x, af.y, af.z, af.w, bf.z, bf.w);
            }
        }
        // fold softmax scale (log2e/8) into q1 (w==0) and q2 (w==2)
        const float sc = (w == 0 || w == 2) ? QSCALE : 1.f;
        __half* dst = dsts[w] + ((size_t)bh*S + s0)*HD;
        #pragma unroll
        for (int nt = 0; nt < 8; nt++) {
            int col = nt*8 + 2*l;
            *(__half2*)&dst[(warp*16+g  )*HD + col] =
                __floats2half2_rn(acc[4*nt  ]*sc, acc[4*nt+1]*sc);
            *(__half2*)&dst[(warp*16+g+8)*HD + col] =
                __floats2half2_rn(acc[4*nt+2]*sc, acc[4*nt+3]*sc);
        }
    }

    // fold-in wo fp32->fp16 conversion (independent; proj precedes out_gemm)
    {
        const int gt = (blockIdx.y * gridDim.x + blockIdx.x) * 256 + tid;  // 0..131071
        const float* src = wo + (size_t)gt * 8;
        __half* dst = g_woh + (size_t)gt * 8;
        #pragma unroll
        for (int j = 0; j < 4; j++) {
            float2 f = *(const float2*)&src[j*2];
            *(__half2*)&dst[j*2] = __floats2half2_rn(f.x, f.y);
        }
    }
}

// ---------------- kernel 2: dual attention (HMMA, f16x2 exp) + groupnorm ------
__device__ __forceinline__ void attn_branch(uint32_t sQu, uint32_t skU, uint32_t svU,
                                            int warp, int lane,
                                            float* o, float& la, float& lb) {
    float s[32];
    #pragma unroll
    for (int i = 0; i < 32; i++) s[i] = 0.f;
    // scores: S(16x64) = Q(16x64) @ K^T
    #pragma unroll
    for (int kc = 0; kc < 4; kc++) {
        uint4 af = lda_frag(sQu, warp*16, kc, lane);
        #pragma unroll
        for (int ntp = 0; ntp < 4; ntp++) {
            uint4 bf = ldb_frag(skU, ntp, kc, lane);
            mma16816(&s[(2*ntp  )*4], af.x, af.y, af.z, af.w, bf.x, bf.y);
            mma16816(&s[(2*ntp+1)*4], af.x, af.y, af.z, af.w, bf.z, bf.w);
        }
    }
    // exp2 via ex2.approx.f16x2 (Q prescaled by log2e/8; scores bounded).
    uint32_t P[16];
    __half2 ha = __float2half2_rn(0.f);
    __half2 hb = ha;
    #pragma unroll
    for (int nt = 0; nt < 8; nt++) {
        __half2 h01 = __floats2half2_rn(s[4*nt  ], s[4*nt+1]);
        __half2 h23 = __floats2half2_rn(s[4*nt+2], s[4*nt+3]);
        uint32_t e01 = ex2_h2(*(uint32_t*)&h01);
        uint32_t e23 = ex2_h2(*(uint32_t*)&h23);
        ha = __hadd2(ha, *(__half2*)&e01);
        hb = __hadd2(hb, *(__half2*)&e23);
        P[2*nt]   = e01;
        P[2*nt+1] = e23;
    }
    {
        float2 fa = __half22float2(ha);
        float2 fb = __half22float2(hb);
        la += fa.x + fa.y;
        lb += fb.x + fb.y;
    }
    // o += P(16x64) @ V(64x64), V B-frags via ldmatrix.x4.trans
    #pragma unroll
    for (int kc = 0; kc < 4; kc++) {
        uint32_t a0 = P[4*kc], a1 = P[4*kc+1], a2 = P[4*kc+2], a3 = P[4*kc+3];
        #pragma unroll
        for (int ntp = 0; ntp < 4; ntp++) {
            uint32_t addr = svU + 2u * ((uint32_t)(kc*16 + (lane & 15)) * QSTR
                                        + ntp*16 + ((lane >> 4) & 1) * 8);
            uint4 bf = ldsm_x4_trans(addr);
            mma16816(&o[(2*ntp  )*4], a0, a1, a2, a3, bf.x, bf.y);
            mma16816(&o[(2*ntp+1)*4], a0, a1, a2, a3, bf.z, bf.w);
        }
    }
}

#define KV_TILE_H (64*QSTR)   // halves per K/V stage array
#define ATHR 128              // attention CTA threads
#define AQ   64               // attention q-rows per CTA

__global__ __launch_bounds__(ATHR, 3) void attn_kernel(const float* __restrict__ gain_p) {
    extern __shared__ __half smh[];
    __half* sQ1 = smh;                  // [AQ][QSTR]
    __half* sQ2 = sQ1 + AQ*QSTR;
    __half* sKV = sQ2 + AQ*QSTR;        // 2 stages x {K1,K2,V} x [64][QSTR]

    const int bh = blockIdx.x;
    const int s0 = blockIdx.y * AQ;
    const int tid = threadIdx.x;
    const int warp = tid >> 5, lane = tid & 31;
    const int g = lane >> 2, l = lane & 3;
    const size_t base = (size_t)bh * S * HD;

    for (int i = tid; i < AQ*32; i += ATHR) {
        int r = i >> 5, c = (i & 31) * 2;
        size_t gi = base + (size_t)(s0 + r)*HD + c;
        *(__half2*)&sQ1[r*QSTR+c] = *(const __half2*)&g_q1h[gi];
        *(__half2*)&sQ2[r*QSTR+c] = *(const __half2*)&g_q2h[gi];
    }

    const uint32_t skv_u = (uint32_t)__cvta_generic_to_shared(sKV);
    const uint32_t q1u = (uint32_t)__cvta_generic_to_shared(sQ1);
    const uint32_t q2u = (uint32_t)__cvta_generic_to_shared(sQ2);
    const __half* gsrc[3] = {g_k1h, g_k2h, g_vph};

    auto issue_tile = [&](int kt, int st) {
        #pragma unroll
        for (int a = 0; a < 3; a++) {
            #pragma unroll
            for (int t = 0; t < 4; t++) {
                int chunk = tid + t*ATHR;       // 512 chunks of 16B per array
                int r = chunk >> 3, c8 = (chunk & 7) * 8;
                uint32_t sa = skv_u + (uint32_t)((st*3 + a)*KV_TILE_H + r*QSTR + c8) * 2;
                cp_async16(sa, gsrc[a] + base + (size_t)(kt*64 + r)*HD + c8);
            }
        }
        cp_commit();
    };

    float o1[32], o2[32];
    #pragma unroll
    for (int i = 0; i < 32; i++) { o1[i] = 0.f; o2[i] = 0.f; }
    float l1a = 0.f, l1b = 0.f, l2a = 0.f, l2b = 0.f;

    const int KT = S/64;
    issue_tile(0, 0);
    for (int kt = 0; kt < KT; kt++) {
        const int cur = kt & 1;
        cp_wait<0>();          // tile kt arrived
        __syncthreads();       // all warps done reading stage cur^1 AND see tile kt
        if (kt + 1 < KT) issue_tile(kt+1, cur ^ 1);
        const uint32_t sk1u = skv_u + (uint32_t)((cur*3    )*KV_TILE_H)*2;
        const uint32_t sk2u = skv_u + (uint32_t)((cur*3 + 1)*KV_TILE_H)*2;
        const uint32_t svu  = skv_u + (uint32_t)((cur*3 + 2)*KV_TILE_H)*2;
        attn_branch(q1u, sk1u, svu, warp, lane, o1, l1a, l1b);
        attn_branch(q2u, sk2u, svu, warp, lane, o2, l2a, l2b);
    }

    l1a += __shfl_xor_sync(0xffffffffu, l1a, 1); l1a += __shfl_xor_sync(0xffffffffu, l1a, 2);
    l1b += __shfl_xor_sync(0xffffffffu, l1b, 1); l1b += __shfl_xor_sync(0xffffffffu, l1b, 2);
    l2a += __shfl_xor_sync(0xffffffffu, l2a, 1); l2a += __shfl_xor_sync(0xffffffffu, l2a, 2);
    l2b += __shfl_xor_sync(0xffffffffu, l2b, 1); l2b += __shfl_xor_sync(0xffffffffu, l2b, 2);

    const float gain = *gain_p;
    const float i1a = 1.f/l1a, i1b = 1.f/l1b, i2a = 1.f/l2a, i2b = 1.f/l2b;

    float va[16], vb[16];
    #pragma unroll
    for (int nt = 0; nt < 8; nt++) {
        va[2*nt]   = o1[4*nt  ]*i1a - gain*o2[4*nt  ]*i2a;
        va[2*nt+1] = o1[4*nt+1]*i1a - gain*o2[4*nt+1]*i2a;
        vb[2*nt]   = o1[4*nt+2]*i1b - gain*o2[4*nt+2]*i2b;
        vb[2*nt+1] = o1[4*nt+3]*i1b - gain*o2[4*nt+3]*i2b;
    }
    float sa = 0.f, sb = 0.f;
    #pragma unroll
    for (int i = 0; i < 16; i++) { sa += va[i]; sb += vb[i]; }
    sa += __shfl_xor_sync(0xffffffffu, sa, 1); sa += __shfl_xor_sync(0xffffffffu, sa, 2);
    sb += __shfl_xor_sync(0xffffffffu, sb, 1); sb += __shfl_xor_sync(0xffffffffu, sb, 2);
    const float ma = sa * (1.f/64.f), mb = sb * (1.f/64.f);
    float qa = 0.f, qb = 0.f;
    #pragma unroll
    for (int i = 0; i < 16; i++) {
        float da = va[i] - ma; qa += da*da;
        float db = vb[i] - mb; qb += db*db;
    }
    qa += __shfl_xor_sync(0xffffffffu, qa, 1); qa += __shfl_xor_sync(0xffffffffu, qa, 2);
    qb += __shfl_xor_sync(0xffffffffu, qb, 1); qb += __shfl_xor_sync(0xffffffffu, qb, 2);
    const float ra = rsqrtf(qa*(1.f/64.f) + EPS);
    const float rb = rsqrtf(qb*(1.f/64.f) + EPS);

    const int b = bh / H, h = bh % H;
    const size_t rowA = (size_t)(b*S + s0 + warp*16 + g)*DIM + h*HD;
    const size_t rowB = rowA + (size_t)8*DIM;
    #pragma unroll
    for (int nt = 0; nt < 8; nt++) {
        int col = nt*8 + 2*l;
        *(__half2*)&g_aoh[rowA + col] = __floats2half2_rn((va[2*nt]-ma)*ra, (va[2*nt+1]-ma)*ra);
        *(__half2*)&g_aoh[rowB + col] = __floats2half2_rn((vb[2*nt]-mb)*rb, (vb[2*nt+1]-mb)*rb);
    }
}

// ---------------- kernel 3: out = ao @ wo^T (HMMA, 128thr, 128x64 tile) -------
#define OG_STAGE_H ((128+64)*QSTR)  // halves per stage (A 128 rows + W 64 rows)

__global__ __launch_bounds__(128, 3) void out_gemm_kernel(float* __restrict__ out) {
    extern __shared__ __half smg[];
    const int n0 = blockIdx.x * 128;
    const int e0 = blockIdx.y * 64;
    const int tid = threadIdx.x;
    const int warp = tid >> 5, lane = tid & 31;
    const int g = lane >> 2, l = lane & 3;
    const uint32_t smg_u = (uint32_t)__cvta_generic_to_shared(smg);

    auto issue_tile = [&](int kt, int st) {
        #pragma unroll
        for (int t = 0; t < 8; t++) {            // A: 128 rows -> 1024 chunks of 16B
            int chunk = tid + t*128;
            int r = chunk >> 3, c8 = (chunk & 7) * 8;
            uint32_t sa = smg_u + (uint32_t)(st*OG_STAGE_H + r*QSTR + c8) * 2;
            cp_async16(sa, &g_aoh[(size_t)(n0+r)*DIM + kt*64 + c8]);
        }
        #pragma unroll
        for (int t = 0; t < 4; t++) {            // W: 64 rows -> 512 chunks
            int chunk = tid + t*128;
            int r = chunk >> 3, c8 = (chunk & 7) * 8;
            uint32_t sa = smg_u + (uint32_t)(st*OG_STAGE_H + 128*QSTR + r*QSTR + c8) * 2;
            cp_async16(sa, &g_woh[(size_t)(e0+r)*DIM + kt*64 + c8]);
        }
        cp_commit();
    };

    float acc[64];
    #pragma unroll
    for (int i = 0; i < 64; i++) acc[i] = 0.f;

    const int KT = DIM/64;
    issue_tile(0, 0);
    for (int kt = 0; kt < KT; kt++) {
        const int cur = kt & 1;
        cp_wait<0>();
        __syncthreads();                          // tile kt visible; other stage free
        if (kt + 1 < KT) issue_tile(kt + 1, cur ^ 1);
        const uint32_t sAu = smg_u + (uint32_t)(cur*OG_STAGE_H)*2;
        const uint32_t sWu = sAu + (uint32_t)(128*QSTR)*2;
        #pragma unroll
        for (int kc = 0; kc < 4; kc++) {
            uint4 af0 = lda_frag(sAu, warp*32,      kc, lane);
            uint4 af1 = lda_frag(sAu, warp*32 + 16, kc, lane);
            #pragma unroll
            for (int ntp = 0; ntp < 4; ntp++) {
                uint4 bf = ldb_frag(sWu, ntp, kc, lane);
                mma16816(&acc[(2*ntp  )*4],      af0.x, af0.y, af0.z, af0.w, bf.x, bf.y);
                mma16816(&acc[(2*ntp+1)*4],      af0.x, af0.y, af0.z, af0.w, bf.z, bf.w);
                mma16816(&acc[(8 + 2*ntp  )*4],  af1.x, af1.y, af1.z, af1.w, bf.x, bf.y);
                mma16816(&acc[(8 + 2*ntp+1)*4],  af1.x, af1.y, af1.z, af1.w, bf.z, bf.w);
            }
        }
    }
    #pragma unroll
    for (int rt = 0; rt < 2; rt++) {
        #pragma unroll
        for (int nt = 0; nt < 8; nt++) {
            const float* a4 = &acc[(rt*8 + nt)*4];
            *(float2*)&out[(size_t)(n0+warp*32+rt*16+g  )*DIM + e0 + nt*8 + 2*l] =
                make_float2(a4[0], a4[1]);
            *(float2*)&out[(size_t)(n0+warp*32+rt*16+g+8)*DIM + e0 + nt*8 + 2*l] =
                make_float2(a4[2], a4[3]);
        }
    }
}

// ---------------- launch ------------------------------------------------------
extern "C" void kernel_launch(void* const* d_in, const int* in_sizes, int n_in,
                              void* d_out, int out_size) {
    const float* q    = (const float*)d_in[0];
    const float* k    = (const float*)d_in[1];
    const float* v    = (const float*)d_in[2];
    const float* wq1  = (const float*)d_in[3];
    const float* wk1  = (const float*)d_in[4];
    const float* wq2  = (const float*)d_in[5];
    const float* wk2  = (const float*)d_in[6];
    const float* wv   = (const float*)d_in[7];
    const float* wo   = (const float*)d_in[8];
    const float* gain = (const float*)d_in[9];
    float* out = (float*)d_out;

    const int smem_proj = (int)((3*128 + 5*64) * QSTR * sizeof(__half));          // 101376
    const int smem_attn = (int)((2*AQ*QSTR + 6*KV_TILE_H) * sizeof(__half));      // 73728
    const int smem_gemm = (int)((2*OG_STAGE_H) * sizeof(__half));                 // 55296
    static bool attr_done = false;
    if (!attr_done) {
        cudaFuncSetAttribute(proj_kernel, cudaFuncAttributeMaxDynamicSharedMemorySize, smem_proj);
        cudaFuncSetAttribute(attn_kernel, cudaFuncAttributeMaxDynamicSharedMemorySize, smem_attn);
        cudaFuncSetAttribute(out_gemm_kernel, cudaFuncAttributeMaxDynamicSharedMemorySize, smem_gemm);
        attr_done = true;
    }

    dim3 gp(B*H, S/128);
    proj_kernel<<<gp, 256, smem_proj>>>(q, k, v, wq1, wk1, wq2, wk2, wv, wo);

    dim3 ga(B*H, S/AQ);
    attn_kernel<<<ga, ATHR, smem_attn>>>(gain);

    dim3 gg(B*S/128, DIM/64);
    out_gemm_kernel<<<gg, 128, smem_gemm>>>(out);
}